// round 13
// baseline (speedup 1.0000x reference)
#include <cuda_runtime.h>
#include <math.h>
#include <stdint.h>

#define Bk   8
#define Nk   1024
#define Dk   256
#define Hk   8
#define DHk  32
#define DFFk 1024
#define BN   (Bk*Nk)   // 8192

// ---------------- scratch ----------------
__device__ float g_Q [Bk*Hk*Nk*DHk];
__device__ float g_K [Bk*Hk*Nk*DHk];
__device__ float g_V [Bk*Hk*Nk*DHk];
__device__ float g_Y [BN*Dk];
__device__ float g_X1[BN*Dk];
__device__ float g_X1r[BN*Dk];
__device__ float g_Hb[(size_t)BN*DFFk];
__device__ float g_RB[(size_t)Bk*Nk*Nk];
__device__ float g_Xr[BN*Dk];
__device__ float g_Wbuf[786432];

// ---------------- helpers ----------------
__device__ __forceinline__ float tfr(float x) {
    unsigned u; asm("cvt.rna.tf32.f32 %0, %1;" : "=r"(u) : "f"(x));
    return __uint_as_float(u);
}
__device__ __forceinline__ unsigned FB(float x) { return __float_as_uint(x); }

__device__ __forceinline__ void mma8(float* d, const unsigned* a, unsigned b0, unsigned b1) {
    asm volatile("mma.sync.aligned.m16n8k8.row.col.f32.tf32.tf32.f32 "
        "{%0,%1,%2,%3},{%4,%5,%6,%7},{%8,%9},{%0,%1,%2,%3};"
        : "+f"(d[0]), "+f"(d[1]), "+f"(d[2]), "+f"(d[3])
        : "r"(a[0]), "r"(a[1]), "r"(a[2]), "r"(a[3]), "r"(b0), "r"(b1));
}

__device__ __forceinline__ void cpa16(void* s, const void* g) {
    uint32_t sa = (uint32_t)__cvta_generic_to_shared(s);
    asm volatile("cp.async.cg.shared.global [%0], [%1], 16;" :: "r"(sa), "l"(g));
}
__device__ __forceinline__ void cpa_commit() { asm volatile("cp.async.commit_group;"); }
template<int N> __device__ __forceinline__ void cpa_wait() {
    asm volatile("cp.async.wait_group %0;" :: "n"(N));
}

__device__ __forceinline__ void load_chunk(float* buf, const float* src, int t) {
#pragma unroll
    for (int i = 0; i < 4; i++) {
        int q = t + i * 256;
        int row = q >> 3, c4 = q & 7;
        cpa16(buf + row * 36 + c4 * 4, src + q * 4);
    }
}

// ---------------- prep ----------------
struct Seg { const float4* s; float4* d; unsigned n; };
struct PrepArgs { Seg seg[7]; };

__global__ void prep_kernel(PrepArgs pa) {
    unsigned i = blockIdx.x * 256 + threadIdx.x;
#pragma unroll
    for (int k = 0; k < 7; k++) {
        if (i < pa.seg[k].n) {
            float4 v = pa.seg[k].s[i];
            v.x = tfr(v.x); v.y = tfr(v.y); v.z = tfr(v.z); v.w = tfr(v.w);
            pa.seg[k].d[i] = v;
            return;
        }
        i -= pa.seg[k].n;
    }
}

// ---------------- bias ----------------
__global__ void bias_kernel(const float4* __restrict__ a, const float4* __restrict__ b,
                            const float4* __restrict__ c) {
    int i = blockIdx.x * blockDim.x + threadIdx.x;
    float4 x = a[i], y = b[i], z = c[i];
    float4 o;
    o.x = x.x + y.x + z.x; o.y = x.y + y.y + z.y;
    o.z = x.z + y.z + z.z; o.w = x.w + y.w + z.w;
    ((float4*)g_RB)[i] = o;
}

// ---------------- gemm_plain ----------------
struct QKVArgs { const float* W[3]; const float* b[3]; float* O[3]; };

#define GP_SMEM_FLOATS (2*4608 + 2*2304)
#define GP_SMEM_BYTES  (GP_SMEM_FLOATS * 4)

template<int MODE>
__global__ __launch_bounds__(256, 2)
void gemm_plain(const float* __restrict__ A, const float* __restrict__ Bw_,
                const float* __restrict__ bias_, float* __restrict__ Out_,
                int K, int NTOT, QKVArgs qa) {
    extern __shared__ float smp[];
    float* Asb = smp;
    float* Bsb = smp + 2 * 4608;
    const int t = threadIdx.x, l = t & 31, wid = t >> 5;
    const int wm = wid & 3, wn = wid >> 2;
    const int mbase = blockIdx.x * 128, nbase = blockIdx.y * 64;

    const float* Bw  = (MODE == 1) ? qa.W[blockIdx.z] : Bw_;
    const float* bias= (MODE == 1) ? qa.b[blockIdx.z] : bias_;
    float* Out       = (MODE == 1) ? qa.O[blockIdx.z] : Out_;

    float acc[2][4][4];
#pragma unroll
    for (int mt = 0; mt < 2; mt++)
#pragma unroll
        for (int nt = 0; nt < 4; nt++)
#pragma unroll
            for (int i = 0; i < 4; i++) acc[mt][nt][i] = 0.f;

    const int nc = K / 32;
    auto stage = [&](int kc, int bi) {
        float* a = Asb + bi * 4608;
        float* b = Bsb + bi * 2304;
#pragma unroll
        for (int i = 0; i < 4; i++) {
            int idx = t + i * 256;
            int r = idx >> 3, q = idx & 7;
            cpa16(a + r * 36 + q * 4, A + (size_t)(mbase + r) * K + kc + q * 4);
        }
#pragma unroll
        for (int i = 0; i < 2; i++) {
            int idx = t + i * 256;
            int k = idx >> 4, q = idx & 15;
            cpa16(b + k * 72 + q * 4, Bw + (size_t)(kc + k) * NTOT + nbase + q * 4);
        }
    };

    stage(0, 0); cpa_commit();
    for (int c = 0; c < nc; c++) {
        if (c + 1 < nc) { stage((c + 1) * 32, (c + 1) & 1); cpa_commit(); cpa_wait<1>(); }
        else            cpa_wait<0>();
        __syncthreads();
        const float* As = Asb + (c & 1) * 4608;
        const float* Bs = Bsb + (c & 1) * 2304;
#pragma unroll
        for (int ks = 0; ks < 4; ks++) {
            unsigned a[2][4];
#pragma unroll
            for (int mt = 0; mt < 2; mt++) {
                const float* p = &As[(wm * 32 + mt * 16 + (l >> 2)) * 36 + ks * 8 + (l & 3)];
                a[mt][0] = FB(p[0]); a[mt][1] = FB(p[8 * 36]);
                a[mt][2] = FB(p[4]); a[mt][3] = FB(p[8 * 36 + 4]);
            }
#pragma unroll
            for (int nt = 0; nt < 4; nt++) {
                const float* p = &Bs[(ks * 8 + (l & 3)) * 72 + wn * 32 + nt * 8 + (l >> 2)];
                unsigned b0 = FB(p[0]), b1 = FB(p[4 * 72]);
                mma8(acc[0][nt], a[0], b0, b1);
                mma8(acc[1][nt], a[1], b0, b1);
            }
        }
        __syncthreads();
    }

#pragma unroll
    for (int mt = 0; mt < 2; mt++)
#pragma unroll
        for (int nt = 0; nt < 4; nt++) {
            int gcol = nbase + wn * 32 + nt * 8 + (l & 3) * 2;
            float bb0 = bias[gcol], bb1 = bias[gcol + 1];
#pragma unroll
            for (int half = 0; half < 2; half++) {
                int grow = mbase + wm * 32 + mt * 16 + (l >> 2) + half * 8;
                float v0 = acc[mt][nt][half * 2 + 0] + bb0;
                float v1 = acc[mt][nt][half * 2 + 1] + bb1;
                if (MODE == 0) {
                    *(float2*)(Out + (size_t)grow * NTOT + gcol) =
                        make_float2(tfr(fmaxf(v0, 0.f)), tfr(fmaxf(v1, 0.f)));
                } else {
                    int h = gcol >> 5, dd = gcol & 31;
                    int bb = grow >> 10, nn = grow & 1023;
                    float* p = Out + ((size_t)((bb * Hk + h) * Nk + nn)) * DHk + dd;
                    *(float2*)p = make_float2(tfr(v0), tfr(v1));
                }
            }
        }
}

// ---------------- gemm_ln32 ----------------
#define LN32_SMEM_FLOATS (2*1152 + 2*8448)
#define LN32_SMEM_BYTES  (LN32_SMEM_FLOATS * 4)

__global__ void gemm_ln32(const float* __restrict__ A, const float* __restrict__ Bw,
                          const float* __restrict__ bias, const float* __restrict__ R,
                          const float* __restrict__ gam, const float* __restrict__ bet,
                          float* __restrict__ Out, float* __restrict__ OutR, int K) {
    extern __shared__ float sm[];
    float* Asb = sm;
    float* Bsb = sm + 2 * 1152;
    const int t = threadIdx.x, l = t & 31, wid = t >> 5;
    const int mbase = blockIdx.x * 32;

    float acc[2][4][4];
#pragma unroll
    for (int mt = 0; mt < 2; mt++)
#pragma unroll
        for (int nt = 0; nt < 4; nt++)
#pragma unroll
            for (int i = 0; i < 4; i++) acc[mt][nt][i] = 0.f;

    const int nc = K / 32;
    auto stage = [&](int kc, int bi) {
        float* a = Asb + bi * 1152;
        float* b = Bsb + bi * 8448;
        {
            int r = t >> 3, q = t & 7;
            cpa16(a + r * 36 + q * 4, A + (size_t)(mbase + r) * K + kc + q * 4);
        }
#pragma unroll
        for (int i = 0; i < 8; i++) {
            int idx = t + i * 256;
            int k = idx >> 6, q = idx & 63;
            cpa16(b + k * 264 + q * 4, Bw + (size_t)(kc + k) * 256 + q * 4);
        }
    };

    stage(0, 0); cpa_commit();
    for (int c = 0; c < nc; c++) {
        if (c + 1 < nc) { stage((c + 1) * 32, (c + 1) & 1); cpa_commit(); cpa_wait<1>(); }
        else            cpa_wait<0>();
        __syncthreads();
        const float* As = Asb + (c & 1) * 1152;
        const float* Bs = Bsb + (c & 1) * 8448;
#pragma unroll
        for (int ks = 0; ks < 4; ks++) {
            unsigned a[2][4];
#pragma unroll
            for (int mt = 0; mt < 2; mt++) {
                const float* p = &As[(mt * 16 + (l >> 2)) * 36 + ks * 8 + (l & 3)];
                a[mt][0] = FB(p[0]); a[mt][1] = FB(p[8 * 36]);
                a[mt][2] = FB(p[4]); a[mt][3] = FB(p[8 * 36 + 4]);
            }
#pragma unroll
            for (int nt = 0; nt < 4; nt++) {
                const float* p = &Bs[(ks * 8 + (l & 3)) * 264 + wid * 32 + nt * 8 + (l >> 2)];
                unsigned b0 = FB(p[0]), b1 = FB(p[4 * 264]);
                mma8(acc[0][nt], a[0], b0, b1);
                mma8(acc[1][nt], a[1], b0, b1);
            }
        }
        __syncthreads();
    }

    float* res = sm;
#pragma unroll
    for (int mt = 0; mt < 2; mt++)
#pragma unroll
        for (int nt = 0; nt < 4; nt++) {
            int m = mt * 16 + (l >> 2);
            int n = wid * 32 + nt * 8 + (l & 3) * 2;
            *(float2*)&res[m * 258 + n] = make_float2(acc[mt][nt][0], acc[mt][nt][1]);
            *(float2*)&res[(m + 8) * 258 + n] = make_float2(acc[mt][nt][2], acc[mt][nt][3]);
        }
    __syncthreads();

#pragma unroll
    for (int i = 0; i < 4; i++) {
        int r = wid * 4 + i;
        int grow = mbase + r;
        float s = 0.f;
        for (int c = l; c < 256; c += 32) {
            float v = res[r * 258 + c] + R[(size_t)grow * 256 + c] + bias[c];
            res[r * 258 + c] = v;
            s += v;
        }
#pragma unroll
        for (int o = 16; o > 0; o >>= 1) s += __shfl_xor_sync(0xffffffffu, s, o);
        float mu = s * (1.f / 256.f);
        float s2 = 0.f;
        for (int c = l; c < 256; c += 32) { float dv = res[r * 258 + c] - mu; s2 += dv * dv; }
#pragma unroll
        for (int o = 16; o > 0; o >>= 1) s2 += __shfl_xor_sync(0xffffffffu, s2, o);
        float rs = rsqrtf(s2 * (1.f / 256.f) + 1e-5f);
        for (int c = l; c < 256; c += 32) {
            float ov = (res[r * 258 + c] - mu) * rs * gam[c] + bet[c];
            Out[(size_t)grow * 256 + c] = ov;
            if (OutR) OutR[(size_t)grow * 256 + c] = tfr(ov);
        }
    }
}

// =====================================================================
// Single-pass flash attention + hidden tail-normalize.
// Per chunk: QK mma -> raw s to attn_out + online (m,l) with Yacc
// rescale -> P@V (V-fragment hoisted). End: cross-warp combine with
// per-warp scale exp(m_w - m_fin)/l_fin, Z-reduce, then barrier-free
// normalize of the CTA's own s tile (L2-resident).
// =====================================================================
#define ATTN_SMEM_FLOATS (2304 + 4*4608 + 512)
#define ATTN_SMEM_BYTES  (ATTN_SMEM_FLOATS * 4)
#define ZSTRIDE 34
#define ZSLOT   (64 * ZSTRIDE)

__global__ __launch_bounds__(256, 2)
void attn_kernel(const float* __restrict__ mask, float* __restrict__ attn_out) {
    extern __shared__ float sm[];
    float* Qs = sm;
    float* Kb[4] = { sm + 2304, sm + 2304 + 4608, sm + 2304 + 2*4608, sm + 2304 + 3*4608 };
    float* st = sm + 2304 + 4*4608;

    const int t = threadIdx.x, l = t & 31, wid = t >> 5;
    const int wm = wid & 1, wn = wid >> 1;
    const int m0 = blockIdx.x * 64, h = blockIdx.y, b = blockIdx.z;

    const float* Qg  = g_Q + ((size_t)((b * Hk + h) * Nk + m0)) * DHk;
    const float* Kg  = g_K + ((size_t)((b * Hk + h) * Nk)) * DHk;
    const float* Vg  = g_V + ((size_t)((b * Hk + h) * Nk)) * DHk;
    const float* RBg = g_RB + ((size_t)(b * Nk + m0)) * Nk;
    const float* mkp = mask + b * Nk;
    const float scale = 0.17677669529663687f;

    // prologue: Q + pair0 {K0,V0}
#pragma unroll
    for (int i = 0; i < 2; i++) {
        int q = t + i * 256;
        cpa16(Qs + (q >> 3) * 36 + (q & 7) * 4, Qg + q * 4);
    }
    load_chunk(Kb[0], Kg, t);
    load_chunk(Kb[1], Vg, t);
    cpa_commit();

    float mL[4], lL[4];
#pragma unroll
    for (int r = 0; r < 4; r++) { mL[r] = -1e30f; lL[r] = 0.f; }

    float Yacc[2][4][4];
#pragma unroll
    for (int mt = 0; mt < 2; mt++)
#pragma unroll
        for (int g = 0; g < 4; g++)
#pragma unroll
            for (int i = 0; i < 4; i++) Yacc[mt][g][i] = 0.f;

    const int rlane = l & 3;
    const int lbase = l & ~3;
    const int slo = lbase | (rlane >> 1);
    const int shi = lbase | ((rlane >> 1) + 2);
    const bool odd = (rlane & 1) != 0;

    // ================= single pass over 8 chunks =================
    for (int c = 0; c < 8; c++) {
        cpa_wait<0>();
        __syncthreads();                 // pair c ready; pair (c+1)&1 free
        if (c < 7) {
            load_chunk(Kb[2 * ((c + 1) & 1)],     Kg + (size_t)(c + 1) * 4096, t);
            load_chunk(Kb[2 * ((c + 1) & 1) + 1], Vg + (size_t)(c + 1) * 4096, t);
            cpa_commit();
        }
        float* kb = Kb[2 * (c & 1)];
        float* vb = Kb[2 * (c & 1) + 1];

        // ---- QK^T ----
        float acc[2][4][4];
#pragma unroll
        for (int mt = 0; mt < 2; mt++)
#pragma unroll
            for (int nt = 0; nt < 4; nt++)
#pragma unroll
                for (int i = 0; i < 4; i++) acc[mt][nt][i] = 0.f;

#pragma unroll
        for (int ks = 0; ks < 4; ks++) {
            unsigned aq[2][4];
#pragma unroll
            for (int mt = 0; mt < 2; mt++) {
                const float* p = &Qs[(wm * 32 + mt * 16 + (l >> 2)) * 36 + ks * 8 + (l & 3)];
                aq[mt][0] = FB(p[0]); aq[mt][1] = FB(p[8 * 36]);
                aq[mt][2] = FB(p[4]); aq[mt][3] = FB(p[8 * 36 + 4]);
            }
#pragma unroll
            for (int nt = 0; nt < 4; nt++) {
                const float* p = &kb[(wn * 32 + nt * 8 + (l >> 2)) * 36 + ks * 8 + (l & 3)];
                unsigned b0 = FB(p[0]), b1 = FB(p[4]);
                mma8(acc[0][nt], aq[0], b0, b1);
                mma8(acc[1][nt], aq[1], b0, b1);
            }
        }

        // ---- s = scale*acc + rb, mask; write raw s; online (m,l); p in acc ----
        float2 mk2[4];
#pragma unroll
        for (int nt = 0; nt < 4; nt++)
            mk2[nt] = *(const float2*)(mkp + c * 128 + wn * 32 + nt * 8 + (l & 3) * 2);

        float fr[4];
#pragma unroll
        for (int r = 0; r < 4; r++) {
            int row = wm * 32 + (r >> 1) * 16 + (r & 1) * 8 + (l >> 2);
            const float* rbrow = RBg + (size_t)row * Nk + c * 128 + wn * 32;
            float* arow = attn_out + (((size_t)((b * Hk + h) * Nk + m0 + row)) * Nk)
                          + c * 128 + wn * 32;
            float vs[8], vmax = -1e30f;
#pragma unroll
            for (int nt = 0; nt < 4; nt++) {
                float2 rb2 = *(const float2*)(rbrow + nt * 8 + (l & 3) * 2);
                int ai = (r & 1) * 2;
                float s0 = acc[r >> 1][nt][ai] * scale + rb2.x;
                float s1 = acc[r >> 1][nt][ai + 1] * scale + rb2.y;
                if (!(mk2[nt].x > 0.f)) s0 = -1e9f;
                if (!(mk2[nt].y > 0.f)) s1 = -1e9f;
                *(float2*)(arow + nt * 8 + (l & 3) * 2) = make_float2(s0, s1);
                vs[nt * 2] = s0; vs[nt * 2 + 1] = s1;
                vmax = fmaxf(vmax, fmaxf(s0, s1));
            }
            // row max across the quad (lanes sharing l>>2)
            vmax = fmaxf(vmax, __shfl_xor_sync(0xffffffffu, vmax, 1));
            vmax = fmaxf(vmax, __shfl_xor_sync(0xffffffffu, vmax, 2));
            float mn = fmaxf(mL[r], vmax);
            float f = __expf(mL[r] - mn);
            float lsum = lL[r] * f;
#pragma unroll
            for (int k = 0; k < 8; k++) {
                float e = __expf(vs[k] - mn);
                lsum += e;
                vs[k] = e;
            }
#pragma unroll
            for (int nt = 0; nt < 4; nt++) {
                int ai = (r & 1) * 2;
                acc[r >> 1][nt][ai]     = tfr(vs[nt * 2]);
                acc[r >> 1][nt][ai + 1] = tfr(vs[nt * 2 + 1]);
            }
            mL[r] = mn; lL[r] = lsum; fr[r] = f;
        }

        // ---- rescale Yacc by fr ----
#pragma unroll
        for (int mt = 0; mt < 2; mt++)
#pragma unroll
            for (int g = 0; g < 4; g++) {
                Yacc[mt][g][0] *= fr[mt * 2];
                Yacc[mt][g][1] *= fr[mt * 2];
                Yacc[mt][g][2] *= fr[mt * 2 + 1];
                Yacc[mt][g][3] *= fr[mt * 2 + 1];
            }

        // ---- P@V (V-fragment hoisted out of mt loop) ----
#pragma unroll
        for (int nt = 0; nt < 4; nt++) {
            unsigned afr[2][4];
#pragma unroll
            for (int mt = 0; mt < 2; mt++) {
                float c0 = acc[mt][nt][0], c1 = acc[mt][nt][1];
                float c2 = acc[mt][nt][2], c3 = acc[mt][nt][3];
                float v00 = __shfl_sync(0xffffffffu, c0, slo);
                float v01 = __shfl_sync(0xffffffffu, c1, slo);
                float v02 = __shfl_sync(0xffffffffu, c2, slo);
                float v03 = __shfl_sync(0xffffffffu, c3, slo);
                float v10 = __shfl_sync(0xffffffffu, c0, shi);
                float v11 = __shfl_sync(0xffffffffu, c1, shi);
                float v12 = __shfl_sync(0xffffffffu, c2, shi);
                float v13 = __shfl_sync(0xffffffffu, c3, shi);
                afr[mt][0] = FB(odd ? v01 : v00);
                afr[mt][1] = FB(odd ? v03 : v02);
                afr[mt][2] = FB(odd ? v11 : v10);
                afr[mt][3] = FB(odd ? v13 : v12);
            }
#pragma unroll
            for (int g = 0; g < 4; g++) {
                const float* pv = &vb[(wn * 32 + nt * 8 + (l & 3)) * 36 + g * 8 + (l >> 2)];
                unsigned b0 = FB(pv[0]), b1 = FB(pv[4 * 36]);
                mma8(Yacc[0][g], afr[0], b0, b1);
                mma8(Yacc[1][g], afr[1], b0, b1);
            }
        }
    }

    // ---- finalize per-warp stats: sum l across quad (m already uniform) ----
#pragma unroll
    for (int r = 0; r < 4; r++) {
        lL[r] += __shfl_xor_sync(0xffffffffu, lL[r], 1);
        lL[r] += __shfl_xor_sync(0xffffffffu, lL[r], 2);
        if ((l & 3) == 0) {
            int row = wm * 32 + (r >> 1) * 16 + (r & 1) * 8 + (l >> 2);
            st[(row * 4 + wn) * 2]     = mL[r];
            st[(row * 4 + wn) * 2 + 1] = lL[r];
        }
    }
    __syncthreads();
    float mF[4], ilF[4], sc[4];
#pragma unroll
    for (int r = 0; r < 4; r++) {
        int row = wm * 32 + (r >> 1) * 16 + (r & 1) * 8 + (l >> 2);
        float m = -1e30f, lv = 0.f;
#pragma unroll
        for (int w2 = 0; w2 < 4; w2++) {
            float m2 = st[(row * 4 + w2) * 2];
            float l2 = st[(row * 4 + w2) * 2 + 1];
            float mn = fmaxf(m, m2);
            lv = lv * __expf(m - mn) + l2 * __expf(m2 - mn);
            m = mn;
        }
        mF[r] = m; ilF[r] = 1.f / lv;
        sc[r] = __expf(mL[r] - m) * ilF[r];   // per-warp combine scale
    }
    __syncthreads();   // st reads done; Kb free for Z

    // ---- Z reduction of scaled partials ----
    float* Z = Kb[0];
#pragma unroll
    for (int mt = 0; mt < 2; mt++)
#pragma unroll
        for (int g = 0; g < 4; g++) {
            int row = wm * 32 + mt * 16 + (l >> 2);
            int col = g * 8 + (l & 3) * 2;
            float* zp = Z + wn * ZSLOT + row * ZSTRIDE + col;
            *(float2*)zp = make_float2(Yacc[mt][g][0] * sc[mt * 2],
                                       Yacc[mt][g][1] * sc[mt * 2]);
            *(float2*)(zp + 8 * ZSTRIDE) = make_float2(Yacc[mt][g][2] * sc[mt * 2 + 1],
                                                       Yacc[mt][g][3] * sc[mt * 2 + 1]);
        }
    __syncthreads();

#pragma unroll
    for (int j = 0; j < 4; j++) {
        int e2 = t * 4 + j;
        int row = e2 >> 4, col = (e2 & 15) * 2;
        const float* zp = Z + row * ZSTRIDE + col;
        float2 z0 = *(const float2*)(zp);
        float2 z1 = *(const float2*)(zp + ZSLOT);
        float2 z2 = *(const float2*)(zp + 2 * ZSLOT);
        float2 z3 = *(const float2*)(zp + 3 * ZSLOT);
        float y0 = tfr(z0.x + z1.x + z2.x + z3.x);
        float y1 = tfr(z0.y + z1.y + z2.y + z3.y);
        float* yp = g_Y + ((size_t)(b * Nk + m0 + row)) * Dk + h * DHk + col;
        *(float2*)yp = make_float2(y0, y1);
    }

    // ---- tail: normalize own s tile in place (no barriers; L2-hot) ----
    for (int c = 0; c < 8; c++) {
#pragma unroll
        for (int r = 0; r < 4; r++) {
            int row = wm * 32 + (r >> 1) * 16 + (r & 1) * 8 + (l >> 2);
            float* arow = attn_out + (((size_t)((b * Hk + h) * Nk + m0 + row)) * Nk)
                          + c * 128 + wn * 32;
            float2 sv[4];
#pragma unroll
            for (int nt = 0; nt < 4; nt++)
                sv[nt] = *(const float2*)(arow + nt * 8 + (l & 3) * 2);
#pragma unroll
            for (int nt = 0; nt < 4; nt++) {
                float p0 = __expf(sv[nt].x - mF[r]) * ilF[r];
                float p1 = __expf(sv[nt].y - mF[r]) * ilF[r];
                *(float2*)(arow + nt * 8 + (l & 3) * 2) = make_float2(p0, p1);
            }
        }
    }
}

// ---------------- launch ----------------
extern "C" void kernel_launch(void* const* d_in, const int* in_sizes, int n_in,
                              void* d_out, int out_size) {
    const float* X    = (const float*)d_in[0];
    const float* mask = (const float*)d_in[1];
    const float* adj  = (const float*)d_in[2];
    const float* attr = (const float*)d_in[3];
    const float* rep  = (const float*)d_in[4];
    const float* Wq = (const float*)d_in[5];  const float* bq = (const float*)d_in[6];
    const float* Wk = (const float*)d_in[7];  const float* bk = (const float*)d_in[8];
    const float* Wv = (const float*)d_in[9];  const float* bv = (const float*)d_in[10];
    const float* Wo = (const float*)d_in[11]; const float* bo = (const float*)d_in[12];
    const float* Wf1 = (const float*)d_in[13]; const float* bf1 = (const float*)d_in[14];
    const float* Wf2 = (const float*)d_in[15]; const float* bf2 = (const float*)d_in[16];
    const float* g1 = (const float*)d_in[17]; const float* b1 = (const float*)d_in[18];
    const float* g2 = (const float*)d_in[19]; const float* b2 = (const float*)d_in[20];

    float* out = (float*)d_out;
    float* attn_out = out + (size_t)BN * Dk;

    cudaFuncSetAttribute(attn_kernel, cudaFuncAttributeMaxDynamicSharedMemorySize,
                         ATTN_SMEM_BYTES);
    cudaFuncSetAttribute(gemm_ln32, cudaFuncAttributeMaxDynamicSharedMemorySize,
                         LN32_SMEM_BYTES);
    cudaFuncSetAttribute(gemm_plain<0>, cudaFuncAttributeMaxDynamicSharedMemorySize,
                         GP_SMEM_BYTES);
    cudaFuncSetAttribute(gemm_plain<1>, cudaFuncAttributeMaxDynamicSharedMemorySize,
                         GP_SMEM_BYTES);

    float* gq;  cudaGetSymbolAddress((void**)&gq,  g_Q);
    float* gk;  cudaGetSymbolAddress((void**)&gk,  g_K);
    float* gv;  cudaGetSymbolAddress((void**)&gv,  g_V);
    float* gy;  cudaGetSymbolAddress((void**)&gy,  g_Y);
    float* gx1; cudaGetSymbolAddress((void**)&gx1, g_X1);
    float* gx1r;cudaGetSymbolAddress((void**)&gx1r,g_X1r);
    float* ghb; cudaGetSymbolAddress((void**)&ghb, g_Hb);
    float* gxr; cudaGetSymbolAddress((void**)&gxr, g_Xr);
    float* gw;  cudaGetSymbolAddress((void**)&gw,  g_Wbuf);

    PrepArgs pa;
    pa.seg[0] = { (const float4*)X,   (float4*)gxr,            524288 };
    pa.seg[1] = { (const float4*)Wq,  (float4*)(gw + 0),        16384 };
    pa.seg[2] = { (const float4*)Wk,  (float4*)(gw + 65536),    16384 };
    pa.seg[3] = { (const float4*)Wv,  (float4*)(gw + 131072),   16384 };
    pa.seg[4] = { (const float4*)Wo,  (float4*)(gw + 196608),   16384 };
    pa.seg[5] = { (const float4*)Wf1, (float4*)(gw + 262144),   65536 };
    pa.seg[6] = { (const float4*)Wf2, (float4*)(gw + 524288),   65536 };
    prep_kernel<<<2816, 256>>>(pa);

    bias_kernel<<<8192, 256>>>((const float4*)adj, (const float4*)attr, (const float4*)rep);

    QKVArgs qa;
    qa.W[0] = gw + 0;      qa.W[1] = gw + 65536;  qa.W[2] = gw + 131072;
    qa.b[0] = bq;          qa.b[1] = bk;          qa.b[2] = bv;
    qa.O[0] = gq;          qa.O[1] = gk;          qa.O[2] = gv;
    QKVArgs qz = {};

    gemm_plain<1><<<dim3(64, 4, 3), 256, GP_SMEM_BYTES>>>(gxr, nullptr, nullptr, nullptr,
                                                          256, 256, qa);

    attn_kernel<<<dim3(16, Hk, Bk), 256, ATTN_SMEM_BYTES>>>(mask, attn_out);

    gemm_ln32<<<256, 256, LN32_SMEM_BYTES>>>(gy, gw + 196608, bo, X, g1, b1, gx1, gx1r, 256);
    gemm_plain<0><<<dim3(64, 16, 1), 256, GP_SMEM_BYTES>>>(gx1r, gw + 262144, bf1, ghb,
                                                           256, 1024, qz);
    gemm_ln32<<<256, 256, LN32_SMEM_BYTES>>>(ghb, gw + 524288, bf2, gx1, g2, b2, out, nullptr, 1024);
}

// round 14
// speedup vs baseline: 1.0528x; 1.0528x over previous
#include <cuda_runtime.h>
#include <math.h>
#include <stdint.h>

#define Bk   8
#define Nk   1024
#define Dk   256
#define Hk   8
#define DHk  32
#define DFFk 1024
#define BN   (Bk*Nk)   // 8192

// ---------------- scratch ----------------
__device__ float g_Q [Bk*Hk*Nk*DHk];
__device__ float g_K [Bk*Hk*Nk*DHk];
__device__ float g_V [Bk*Hk*Nk*DHk];
__device__ float g_Y [BN*Dk];
__device__ float g_X1[BN*Dk];
__device__ float g_X1r[BN*Dk];
__device__ float g_Hb[(size_t)BN*DFFk];
__device__ float g_RB[(size_t)Bk*Nk*Nk];
__device__ float g_Xr[BN*Dk];
__device__ float g_Wbuf[786432];

// ---------------- helpers ----------------
__device__ __forceinline__ float tfr(float x) {
    unsigned u; asm("cvt.rna.tf32.f32 %0, %1;" : "=r"(u) : "f"(x));
    return __uint_as_float(u);
}
__device__ __forceinline__ unsigned FB(float x) { return __float_as_uint(x); }

__device__ __forceinline__ void mma8(float* d, const unsigned* a, unsigned b0, unsigned b1) {
    asm volatile("mma.sync.aligned.m16n8k8.row.col.f32.tf32.tf32.f32 "
        "{%0,%1,%2,%3},{%4,%5,%6,%7},{%8,%9},{%0,%1,%2,%3};"
        : "+f"(d[0]), "+f"(d[1]), "+f"(d[2]), "+f"(d[3])
        : "r"(a[0]), "r"(a[1]), "r"(a[2]), "r"(a[3]), "r"(b0), "r"(b1));
}

__device__ __forceinline__ void cpa16(void* s, const void* g) {
    uint32_t sa = (uint32_t)__cvta_generic_to_shared(s);
    asm volatile("cp.async.cg.shared.global [%0], [%1], 16;" :: "r"(sa), "l"(g));
}
__device__ __forceinline__ void cpa_commit() { asm volatile("cp.async.commit_group;"); }
template<int N> __device__ __forceinline__ void cpa_wait() {
    asm volatile("cp.async.wait_group %0;" :: "n"(N));
}

__device__ __forceinline__ void load_chunk(float* buf, const float* src, int t) {
#pragma unroll
    for (int i = 0; i < 4; i++) {
        int q = t + i * 256;
        int row = q >> 3, c4 = q & 7;
        cpa16(buf + row * 36 + c4 * 4, src + q * 4);
    }
}

// ---------------- prep ----------------
struct Seg { const float4* s; float4* d; unsigned n; };
struct PrepArgs { Seg seg[7]; };

__global__ void prep_kernel(PrepArgs pa) {
    unsigned i = blockIdx.x * 256 + threadIdx.x;
#pragma unroll
    for (int k = 0; k < 7; k++) {
        if (i < pa.seg[k].n) {
            float4 v = pa.seg[k].s[i];
            v.x = tfr(v.x); v.y = tfr(v.y); v.z = tfr(v.z); v.w = tfr(v.w);
            pa.seg[k].d[i] = v;
            return;
        }
        i -= pa.seg[k].n;
    }
}

// ---------------- bias ----------------
__global__ void bias_kernel(const float4* __restrict__ a, const float4* __restrict__ b,
                            const float4* __restrict__ c) {
    int i = blockIdx.x * blockDim.x + threadIdx.x;
    float4 x = a[i], y = b[i], z = c[i];
    float4 o;
    o.x = x.x + y.x + z.x; o.y = x.y + y.y + z.y;
    o.z = x.z + y.z + z.z; o.w = x.w + y.w + z.w;
    ((float4*)g_RB)[i] = o;
}

// ---------------- gemm_plain ----------------
struct QKVArgs { const float* W[3]; const float* b[3]; float* O[3]; };

#define GP_SMEM_FLOATS (2*4608 + 2*2304)
#define GP_SMEM_BYTES  (GP_SMEM_FLOATS * 4)

template<int MODE>
__global__ __launch_bounds__(256, 2)
void gemm_plain(const float* __restrict__ A, const float* __restrict__ Bw_,
                const float* __restrict__ bias_, float* __restrict__ Out_,
                int K, int NTOT, QKVArgs qa) {
    extern __shared__ float smp[];
    float* Asb = smp;
    float* Bsb = smp + 2 * 4608;
    const int t = threadIdx.x, l = t & 31, wid = t >> 5;
    const int wm = wid & 3, wn = wid >> 2;
    const int mbase = blockIdx.x * 128, nbase = blockIdx.y * 64;

    const float* Bw  = (MODE == 1) ? qa.W[blockIdx.z] : Bw_;
    const float* bias= (MODE == 1) ? qa.b[blockIdx.z] : bias_;
    float* Out       = (MODE == 1) ? qa.O[blockIdx.z] : Out_;

    float acc[2][4][4];
#pragma unroll
    for (int mt = 0; mt < 2; mt++)
#pragma unroll
        for (int nt = 0; nt < 4; nt++)
#pragma unroll
            for (int i = 0; i < 4; i++) acc[mt][nt][i] = 0.f;

    const int nc = K / 32;
    auto stage = [&](int kc, int bi) {
        float* a = Asb + bi * 4608;
        float* b = Bsb + bi * 2304;
#pragma unroll
        for (int i = 0; i < 4; i++) {
            int idx = t + i * 256;
            int r = idx >> 3, q = idx & 7;
            cpa16(a + r * 36 + q * 4, A + (size_t)(mbase + r) * K + kc + q * 4);
        }
#pragma unroll
        for (int i = 0; i < 2; i++) {
            int idx = t + i * 256;
            int k = idx >> 4, q = idx & 15;
            cpa16(b + k * 72 + q * 4, Bw + (size_t)(kc + k) * NTOT + nbase + q * 4);
        }
    };

    stage(0, 0); cpa_commit();
    for (int c = 0; c < nc; c++) {
        if (c + 1 < nc) { stage((c + 1) * 32, (c + 1) & 1); cpa_commit(); cpa_wait<1>(); }
        else            cpa_wait<0>();
        __syncthreads();
        const float* As = Asb + (c & 1) * 4608;
        const float* Bs = Bsb + (c & 1) * 2304;
#pragma unroll
        for (int ks = 0; ks < 4; ks++) {
            unsigned a[2][4];
#pragma unroll
            for (int mt = 0; mt < 2; mt++) {
                const float* p = &As[(wm * 32 + mt * 16 + (l >> 2)) * 36 + ks * 8 + (l & 3)];
                a[mt][0] = FB(p[0]); a[mt][1] = FB(p[8 * 36]);
                a[mt][2] = FB(p[4]); a[mt][3] = FB(p[8 * 36 + 4]);
            }
#pragma unroll
            for (int nt = 0; nt < 4; nt++) {
                const float* p = &Bs[(ks * 8 + (l & 3)) * 72 + wn * 32 + nt * 8 + (l >> 2)];
                unsigned b0 = FB(p[0]), b1 = FB(p[4 * 72]);
                mma8(acc[0][nt], a[0], b0, b1);
                mma8(acc[1][nt], a[1], b0, b1);
            }
        }
        __syncthreads();
    }

#pragma unroll
    for (int mt = 0; mt < 2; mt++)
#pragma unroll
        for (int nt = 0; nt < 4; nt++) {
            int gcol = nbase + wn * 32 + nt * 8 + (l & 3) * 2;
            float bb0 = bias[gcol], bb1 = bias[gcol + 1];
#pragma unroll
            for (int half = 0; half < 2; half++) {
                int grow = mbase + wm * 32 + mt * 16 + (l >> 2) + half * 8;
                float v0 = acc[mt][nt][half * 2 + 0] + bb0;
                float v1 = acc[mt][nt][half * 2 + 1] + bb1;
                if (MODE == 0) {
                    *(float2*)(Out + (size_t)grow * NTOT + gcol) =
                        make_float2(tfr(fmaxf(v0, 0.f)), tfr(fmaxf(v1, 0.f)));
                } else {
                    int h = gcol >> 5, dd = gcol & 31;
                    int bb = grow >> 10, nn = grow & 1023;
                    float* p = Out + ((size_t)((bb * Hk + h) * Nk + nn)) * DHk + dd;
                    *(float2*)p = make_float2(tfr(v0), tfr(v1));
                }
            }
        }
}

// ---------------- gemm_ln32 ----------------
#define LN32_SMEM_FLOATS (2*1152 + 2*8448)
#define LN32_SMEM_BYTES  (LN32_SMEM_FLOATS * 4)

__global__ void gemm_ln32(const float* __restrict__ A, const float* __restrict__ Bw,
                          const float* __restrict__ bias, const float* __restrict__ R,
                          const float* __restrict__ gam, const float* __restrict__ bet,
                          float* __restrict__ Out, float* __restrict__ OutR, int K) {
    extern __shared__ float sm[];
    float* Asb = sm;
    float* Bsb = sm + 2 * 1152;
    const int t = threadIdx.x, l = t & 31, wid = t >> 5;
    const int mbase = blockIdx.x * 32;

    float acc[2][4][4];
#pragma unroll
    for (int mt = 0; mt < 2; mt++)
#pragma unroll
        for (int nt = 0; nt < 4; nt++)
#pragma unroll
            for (int i = 0; i < 4; i++) acc[mt][nt][i] = 0.f;

    const int nc = K / 32;
    auto stage = [&](int kc, int bi) {
        float* a = Asb + bi * 1152;
        float* b = Bsb + bi * 8448;
        {
            int r = t >> 3, q = t & 7;
            cpa16(a + r * 36 + q * 4, A + (size_t)(mbase + r) * K + kc + q * 4);
        }
#pragma unroll
        for (int i = 0; i < 8; i++) {
            int idx = t + i * 256;
            int k = idx >> 6, q = idx & 63;
            cpa16(b + k * 264 + q * 4, Bw + (size_t)(kc + k) * 256 + q * 4);
        }
    };

    stage(0, 0); cpa_commit();
    for (int c = 0; c < nc; c++) {
        if (c + 1 < nc) { stage((c + 1) * 32, (c + 1) & 1); cpa_commit(); cpa_wait<1>(); }
        else            cpa_wait<0>();
        __syncthreads();
        const float* As = Asb + (c & 1) * 1152;
        const float* Bs = Bsb + (c & 1) * 8448;
#pragma unroll
        for (int ks = 0; ks < 4; ks++) {
            unsigned a[2][4];
#pragma unroll
            for (int mt = 0; mt < 2; mt++) {
                const float* p = &As[(mt * 16 + (l >> 2)) * 36 + ks * 8 + (l & 3)];
                a[mt][0] = FB(p[0]); a[mt][1] = FB(p[8 * 36]);
                a[mt][2] = FB(p[4]); a[mt][3] = FB(p[8 * 36 + 4]);
            }
#pragma unroll
            for (int nt = 0; nt < 4; nt++) {
                const float* p = &Bs[(ks * 8 + (l & 3)) * 264 + wid * 32 + nt * 8 + (l >> 2)];
                unsigned b0 = FB(p[0]), b1 = FB(p[4 * 264]);
                mma8(acc[0][nt], a[0], b0, b1);
                mma8(acc[1][nt], a[1], b0, b1);
            }
        }
        __syncthreads();
    }

    float* res = sm;
#pragma unroll
    for (int mt = 0; mt < 2; mt++)
#pragma unroll
        for (int nt = 0; nt < 4; nt++) {
            int m = mt * 16 + (l >> 2);
            int n = wid * 32 + nt * 8 + (l & 3) * 2;
            *(float2*)&res[m * 258 + n] = make_float2(acc[mt][nt][0], acc[mt][nt][1]);
            *(float2*)&res[(m + 8) * 258 + n] = make_float2(acc[mt][nt][2], acc[mt][nt][3]);
        }
    __syncthreads();

#pragma unroll
    for (int i = 0; i < 4; i++) {
        int r = wid * 4 + i;
        int grow = mbase + r;
        float s = 0.f;
        for (int c = l; c < 256; c += 32) {
            float v = res[r * 258 + c] + R[(size_t)grow * 256 + c] + bias[c];
            res[r * 258 + c] = v;
            s += v;
        }
#pragma unroll
        for (int o = 16; o > 0; o >>= 1) s += __shfl_xor_sync(0xffffffffu, s, o);
        float mu = s * (1.f / 256.f);
        float s2 = 0.f;
        for (int c = l; c < 256; c += 32) { float dv = res[r * 258 + c] - mu; s2 += dv * dv; }
#pragma unroll
        for (int o = 16; o > 0; o >>= 1) s2 += __shfl_xor_sync(0xffffffffu, s2, o);
        float rs = rsqrtf(s2 * (1.f / 256.f) + 1e-5f);
        for (int c = l; c < 256; c += 32) {
            float ov = (res[r * 258 + c] - mu) * rs * gam[c] + bet[c];
            Out[(size_t)grow * 256 + c] = ov;
            if (OutR) OutR[(size_t)grow * 256 + c] = tfr(ov);
        }
    }
}

// =====================================================================
// Fused attention — R12 proven form (two-pass recompute, Q-hoist in
// pass 1) + shared V-fragments in pass-2 P@V (halves its LDS count).
// =====================================================================
#define ATTN_SMEM_FLOATS (2304 + 4*4608 + 512)
#define ATTN_SMEM_BYTES  (ATTN_SMEM_FLOATS * 4)
#define ZSTRIDE 34
#define ZSLOT   (64 * ZSTRIDE)

__global__ __launch_bounds__(256, 2)
void attn_kernel(const float* __restrict__ mask, float* __restrict__ attn_out) {
    extern __shared__ float sm[];
    float* Qs = sm;
    float* Kb[4] = { sm + 2304, sm + 2304 + 4608, sm + 2304 + 2*4608, sm + 2304 + 3*4608 };
    float* st = sm + 2304 + 4*4608;

    const int t = threadIdx.x, l = t & 31, wid = t >> 5;
    const int wm = wid & 1, wn = wid >> 1;
    const int m0 = blockIdx.x * 64, h = blockIdx.y, b = blockIdx.z;

    const float* Qg  = g_Q + ((size_t)((b * Hk + h) * Nk + m0)) * DHk;
    const float* Kg  = g_K + ((size_t)((b * Hk + h) * Nk)) * DHk;
    const float* Vg  = g_V + ((size_t)((b * Hk + h) * Nk)) * DHk;
    const float* RBg = g_RB + ((size_t)(b * Nk + m0)) * Nk;
    const float* mkp = mask + b * Nk;
    const float scale = 0.17677669529663687f;

#pragma unroll
    for (int i = 0; i < 2; i++) {
        int q = t + i * 256;
        cpa16(Qs + (q >> 3) * 36 + (q & 7) * 4, Qg + q * 4);
    }
    load_chunk(Kb[0], Kg, t); cpa_commit();
    load_chunk(Kb[1], Kg + 4096, t); cpa_commit();
    load_chunk(Kb[2], Kg + 2 * 4096, t); cpa_commit();

    float mL[4], lL[4];
#pragma unroll
    for (int r = 0; r < 4; r++) { mL[r] = -1e30f; lL[r] = 0.f; }

    // ---- PASS 1 with hoisted Q fragments ----
    {
        cpa_wait<2>(); __syncthreads();   // Q (group 0) resident
        unsigned aqh[4][2][4];
#pragma unroll
        for (int ks = 0; ks < 4; ks++)
#pragma unroll
            for (int mt = 0; mt < 2; mt++) {
                const float* p = &Qs[(wm * 32 + mt * 16 + (l >> 2)) * 36 + ks * 8 + (l & 3)];
                aqh[ks][mt][0] = FB(p[0]); aqh[ks][mt][1] = FB(p[8 * 36]);
                aqh[ks][mt][2] = FB(p[4]); aqh[ks][mt][3] = FB(p[8 * 36 + 4]);
            }

        // ledger: g0..g2 prologue, g3..g7 at c=0..4; tiers 2/2/2/2/2/2/1/0.
        for (int c = 0; c < 8; c++) {
            if (c < 6)       cpa_wait<2>();
            else if (c == 6) cpa_wait<1>();
            else             cpa_wait<0>();
            __syncthreads();
            if (c < 5) { load_chunk(Kb[(c + 3) & 3], Kg + (size_t)(c + 3) * 4096, t); cpa_commit(); }

            float* kb = Kb[c & 3];
            float acc[2][4][4];
#pragma unroll
            for (int mt = 0; mt < 2; mt++)
#pragma unroll
                for (int nt = 0; nt < 4; nt++)
#pragma unroll
                    for (int i = 0; i < 4; i++) acc[mt][nt][i] = 0.f;

#pragma unroll
            for (int ks = 0; ks < 4; ks++)
#pragma unroll
                for (int nt = 0; nt < 4; nt++) {
                    const float* p = &kb[(wn * 32 + nt * 8 + (l >> 2)) * 36 + ks * 8 + (l & 3)];
                    unsigned b0 = FB(p[0]), b1 = FB(p[4]);
                    mma8(acc[0][nt], aqh[ks][0], b0, b1);
                    mma8(acc[1][nt], aqh[ks][1], b0, b1);
                }

            float2 mk2[4];
#pragma unroll
            for (int nt = 0; nt < 4; nt++)
                mk2[nt] = *(const float2*)(mkp + c * 128 + wn * 32 + nt * 8 + (l & 3) * 2);

#pragma unroll
            for (int r = 0; r < 4; r++) {
                int row = wm * 32 + (r >> 1) * 16 + (r & 1) * 8 + (l >> 2);
                const float* rbrow = RBg + (size_t)row * Nk + c * 128 + wn * 32;
                float vs[8], vmax = -1e30f;
#pragma unroll
                for (int nt = 0; nt < 4; nt++) {
                    float2 rb2 = *(const float2*)(rbrow + nt * 8 + (l & 3) * 2);
                    int ai = (r & 1) * 2;
                    float s0 = acc[r >> 1][nt][ai] * scale + rb2.x;
                    float s1 = acc[r >> 1][nt][ai + 1] * scale + rb2.y;
                    if (!(mk2[nt].x > 0.f)) s0 = -1e9f;
                    if (!(mk2[nt].y > 0.f)) s1 = -1e9f;
                    vs[nt * 2] = s0; vs[nt * 2 + 1] = s1;
                    vmax = fmaxf(vmax, fmaxf(s0, s1));
                }
                float mn = fmaxf(mL[r], vmax);
                float lsum = lL[r] * __expf(mL[r] - mn);
#pragma unroll
                for (int k = 0; k < 8; k++) lsum += __expf(vs[k] - mn);
                mL[r] = mn; lL[r] = lsum;
            }
        }
    }

    // ---- merge stats ----
#pragma unroll
    for (int r = 0; r < 4; r++) {
        float m = mL[r], lv = lL[r];
#pragma unroll
        for (int o = 1; o <= 2; o <<= 1) {
            float m2 = __shfl_xor_sync(0xffffffffu, m, o);
            float l2 = __shfl_xor_sync(0xffffffffu, lv, o);
            float mn = fmaxf(m, m2);
            lv = lv * __expf(m - mn) + l2 * __expf(m2 - mn);
            m = mn;
        }
        if ((l & 3) == 0) {
            int row = wm * 32 + (r >> 1) * 16 + (r & 1) * 8 + (l >> 2);
            st[(row * 4 + wn) * 2]     = m;
            st[(row * 4 + wn) * 2 + 1] = lv;
        }
    }
    __syncthreads();
    float mF[4], ilF[4];
#pragma unroll
    for (int r = 0; r < 4; r++) {
        int row = wm * 32 + (r >> 1) * 16 + (r & 1) * 8 + (l >> 2);
        float m = -1e30f, lv = 0.f;
#pragma unroll
        for (int w2 = 0; w2 < 4; w2++) {
            float m2 = st[(row * 4 + w2) * 2];
            float l2 = st[(row * 4 + w2) * 2 + 1];
            float mn = fmaxf(m, m2);
            lv = lv * __expf(m - mn) + l2 * __expf(m2 - mn);
            m = mn;
        }
        mF[r] = m; ilF[r] = 1.f / lv;
    }
    __syncthreads();

    // ---- pass 2 prologue: pair0 = {K0,V0} ----
    load_chunk(Kb[0], Kg, t);
    load_chunk(Kb[1], Vg, t);
    cpa_commit();

    float Yacc[2][4][4];
#pragma unroll
    for (int mt = 0; mt < 2; mt++)
#pragma unroll
        for (int g = 0; g < 4; g++)
#pragma unroll
            for (int i = 0; i < 4; i++) Yacc[mt][g][i] = 0.f;

    const int rlane = l & 3;
    const int lbase = l & ~3;
    const int slo = lbase | (rlane >> 1);
    const int shi = lbase | ((rlane >> 1) + 2);
    const bool odd = (rlane & 1) != 0;

    // ---- PASS 2 (recompute; shared V-fragments in P@V) ----
    for (int c = 0; c < 8; c++) {
        cpa_wait<0>();
        __syncthreads();
        if (c < 7) {
            load_chunk(Kb[2 * ((c + 1) & 1)],     Kg + (size_t)(c + 1) * 4096, t);
            load_chunk(Kb[2 * ((c + 1) & 1) + 1], Vg + (size_t)(c + 1) * 4096, t);
            cpa_commit();
        }
        float* kb = Kb[2 * (c & 1)];
        float* vb = Kb[2 * (c & 1) + 1];

        float acc[2][4][4];
#pragma unroll
        for (int mt = 0; mt < 2; mt++)
#pragma unroll
            for (int nt = 0; nt < 4; nt++)
#pragma unroll
                for (int i = 0; i < 4; i++) acc[mt][nt][i] = 0.f;

#pragma unroll
        for (int ks = 0; ks < 4; ks++) {
            unsigned aq[2][4];
#pragma unroll
            for (int mt = 0; mt < 2; mt++) {
                const float* p = &Qs[(wm * 32 + mt * 16 + (l >> 2)) * 36 + ks * 8 + (l & 3)];
                aq[mt][0] = FB(p[0]); aq[mt][1] = FB(p[8 * 36]);
                aq[mt][2] = FB(p[4]); aq[mt][3] = FB(p[8 * 36 + 4]);
            }
#pragma unroll
            for (int nt = 0; nt < 4; nt++) {
                const float* p = &kb[(wn * 32 + nt * 8 + (l >> 2)) * 36 + ks * 8 + (l & 3)];
                unsigned b0 = FB(p[0]), b1 = FB(p[4]);
                mma8(acc[0][nt], aq[0], b0, b1);
                mma8(acc[1][nt], aq[1], b0, b1);
            }
        }

        float2 mk2[4];
#pragma unroll
        for (int nt = 0; nt < 4; nt++)
            mk2[nt] = *(const float2*)(mkp + c * 128 + wn * 32 + nt * 8 + (l & 3) * 2);

#pragma unroll
        for (int r = 0; r < 4; r++) {
            int row = wm * 32 + (r >> 1) * 16 + (r & 1) * 8 + (l >> 2);
            const float* rbrow = RBg + (size_t)row * Nk + c * 128 + wn * 32;
            float* arow = attn_out + (((size_t)((b * Hk + h) * Nk + m0 + row)) * Nk)
                          + c * 128 + wn * 32;
#pragma unroll
            for (int nt = 0; nt < 4; nt++) {
                float2 rb2 = *(const float2*)(rbrow + nt * 8 + (l & 3) * 2);
                int ai = (r & 1) * 2;
                float s0 = acc[r >> 1][nt][ai] * scale + rb2.x;
                float s1 = acc[r >> 1][nt][ai + 1] * scale + rb2.y;
                if (!(mk2[nt].x > 0.f)) s0 = -1e9f;
                if (!(mk2[nt].y > 0.f)) s1 = -1e9f;
                float p0 = __expf(s0 - mF[r]) * ilF[r];
                float p1 = __expf(s1 - mF[r]) * ilF[r];
                *(float2*)(arow + nt * 8 + (l & 3) * 2) = make_float2(p0, p1);
                acc[r >> 1][nt][ai]     = tfr(p0);
                acc[r >> 1][nt][ai + 1] = tfr(p1);
            }
        }

        // ---- P@V: nt-outer, V-fragments shared across mt ----
#pragma unroll
        for (int nt = 0; nt < 4; nt++) {
            unsigned afr[2][4];
#pragma unroll
            for (int mt = 0; mt < 2; mt++) {
                float c0 = acc[mt][nt][0], c1 = acc[mt][nt][1];
                float c2 = acc[mt][nt][2], c3 = acc[mt][nt][3];
                float v00 = __shfl_sync(0xffffffffu, c0, slo);
                float v01 = __shfl_sync(0xffffffffu, c1, slo);
                float v02 = __shfl_sync(0xffffffffu, c2, slo);
                float v03 = __shfl_sync(0xffffffffu, c3, slo);
                float v10 = __shfl_sync(0xffffffffu, c0, shi);
                float v11 = __shfl_sync(0xffffffffu, c1, shi);
                float v12 = __shfl_sync(0xffffffffu, c2, shi);
                float v13 = __shfl_sync(0xffffffffu, c3, shi);
                afr[mt][0] = FB(odd ? v01 : v00);
                afr[mt][1] = FB(odd ? v03 : v02);
                afr[mt][2] = FB(odd ? v11 : v10);
                afr[mt][3] = FB(odd ? v13 : v12);
            }
#pragma unroll
            for (int g = 0; g < 4; g++) {
                const float* pv = &vb[(wn * 32 + nt * 8 + (l & 3)) * 36 + g * 8 + (l >> 2)];
                unsigned b0 = FB(pv[0]), b1 = FB(pv[4 * 36]);
                mma8(Yacc[0][g], afr[0], b0, b1);
                mma8(Yacc[1][g], afr[1], b0, b1);
            }
        }
    }

    // ---- final cross-warp Y reduction ----
    float* Z = Kb[0];
    __syncthreads();
#pragma unroll
    for (int mt = 0; mt < 2; mt++)
#pragma unroll
        for (int g = 0; g < 4; g++) {
            int row = wm * 32 + mt * 16 + (l >> 2);
            int col = g * 8 + (l & 3) * 2;
            float* zp = Z + wn * ZSLOT + row * ZSTRIDE + col;
            *(float2*)zp = make_float2(Yacc[mt][g][0], Yacc[mt][g][1]);
            *(float2*)(zp + 8 * ZSTRIDE) = make_float2(Yacc[mt][g][2], Yacc[mt][g][3]);
        }
    __syncthreads();

#pragma unroll
    for (int j = 0; j < 4; j++) {
        int e2 = t * 4 + j;
        int row = e2 >> 4, col = (e2 & 15) * 2;
        const float* zp = Z + row * ZSTRIDE + col;
        float2 z0 = *(const float2*)(zp);
        float2 z1 = *(const float2*)(zp + ZSLOT);
        float2 z2 = *(const float2*)(zp + 2 * ZSLOT);
        float2 z3 = *(const float2*)(zp + 3 * ZSLOT);
        float y0 = tfr(z0.x + z1.x + z2.x + z3.x);
        float y1 = tfr(z0.y + z1.y + z2.y + z3.y);
        float* yp = g_Y + ((size_t)(b * Nk + m0 + row)) * Dk + h * DHk + col;
        *(float2*)yp = make_float2(y0, y1);
    }
}

// ---------------- launch ----------------
extern "C" void kernel_launch(void* const* d_in, const int* in_sizes, int n_in,
                              void* d_out, int out_size) {
    const float* X    = (const float*)d_in[0];
    const float* mask = (const float*)d_in[1];
    const float* adj  = (const float*)d_in[2];
    const float* attr = (const float*)d_in[3];
    const float* rep  = (const float*)d_in[4];
    const float* Wq = (const float*)d_in[5];  const float* bq = (const float*)d_in[6];
    const float* Wk = (const float*)d_in[7];  const float* bk = (const float*)d_in[8];
    const float* Wv = (const float*)d_in[9];  const float* bv = (const float*)d_in[10];
    const float* Wo = (const float*)d_in[11]; const float* bo = (const float*)d_in[12];
    const float* Wf1 = (const float*)d_in[13]; const float* bf1 = (const float*)d_in[14];
    const float* Wf2 = (const float*)d_in[15]; const float* bf2 = (const float*)d_in[16];
    const float* g1 = (const float*)d_in[17]; const float* b1 = (const float*)d_in[18];
    const float* g2 = (const float*)d_in[19]; const float* b2 = (const float*)d_in[20];

    float* out = (float*)d_out;
    float* attn_out = out + (size_t)BN * Dk;

    cudaFuncSetAttribute(attn_kernel, cudaFuncAttributeMaxDynamicSharedMemorySize,
                         ATTN_SMEM_BYTES);
    cudaFuncSetAttribute(gemm_ln32, cudaFuncAttributeMaxDynamicSharedMemorySize,
                         LN32_SMEM_BYTES);
    cudaFuncSetAttribute(gemm_plain<0>, cudaFuncAttributeMaxDynamicSharedMemorySize,
                         GP_SMEM_BYTES);
    cudaFuncSetAttribute(gemm_plain<1>, cudaFuncAttributeMaxDynamicSharedMemorySize,
                         GP_SMEM_BYTES);

    float* gq;  cudaGetSymbolAddress((void**)&gq,  g_Q);
    float* gk;  cudaGetSymbolAddress((void**)&gk,  g_K);
    float* gv;  cudaGetSymbolAddress((void**)&gv,  g_V);
    float* gy;  cudaGetSymbolAddress((void**)&gy,  g_Y);
    float* gx1; cudaGetSymbolAddress((void**)&gx1, g_X1);
    float* gx1r;cudaGetSymbolAddress((void**)&gx1r,g_X1r);
    float* ghb; cudaGetSymbolAddress((void**)&ghb, g_Hb);
    float* gxr; cudaGetSymbolAddress((void**)&gxr, g_Xr);
    float* gw;  cudaGetSymbolAddress((void**)&gw,  g_Wbuf);

    PrepArgs pa;
    pa.seg[0] = { (const float4*)X,   (float4*)gxr,            524288 };
    pa.seg[1] = { (const float4*)Wq,  (float4*)(gw + 0),        16384 };
    pa.seg[2] = { (const float4*)Wk,  (float4*)(gw + 65536),    16384 };
    pa.seg[3] = { (const float4*)Wv,  (float4*)(gw + 131072),   16384 };
    pa.seg[4] = { (const float4*)Wo,  (float4*)(gw + 196608),   16384 };
    pa.seg[5] = { (const float4*)Wf1, (float4*)(gw + 262144),   65536 };
    pa.seg[6] = { (const float4*)Wf2, (float4*)(gw + 524288),   65536 };
    prep_kernel<<<2816, 256>>>(pa);

    bias_kernel<<<8192, 256>>>((const float4*)adj, (const float4*)attr, (const float4*)rep);

    QKVArgs qa;
    qa.W[0] = gw + 0;      qa.W[1] = gw + 65536;  qa.W[2] = gw + 131072;
    qa.b[0] = bq;          qa.b[1] = bk;          qa.b[2] = bv;
    qa.O[0] = gq;          qa.O[1] = gk;          qa.O[2] = gv;
    QKVArgs qz = {};

    gemm_plain<1><<<dim3(64, 4, 3), 256, GP_SMEM_BYTES>>>(gxr, nullptr, nullptr, nullptr,
                                                          256, 256, qa);

    attn_kernel<<<dim3(16, Hk, Bk), 256, ATTN_SMEM_BYTES>>>(mask, attn_out);

    gemm_ln32<<<256, 256, LN32_SMEM_BYTES>>>(gy, gw + 196608, bo, X, g1, b1, gx1, gx1r, 256);
    gemm_plain<0><<<dim3(64, 16, 1), 256, GP_SMEM_BYTES>>>(gx1r, gw + 262144, bf1, ghb,
                                                           256, 1024, qz);
    gemm_ln32<<<256, 256, LN32_SMEM_BYTES>>>(ghb, gw + 524288, bf2, gx1, g2, b2, out, nullptr, 1024);
}